// round 14
// baseline (speedup 1.0000x reference)
#include <cuda_runtime.h>
#include <cuda_fp16.h>

// Problem constants (fixed by the reference)
#define Nn   10000      // nodes
#define Ee   80000      // edges (excl. self loops)
#define Gg   16         // B*DAYS graphs
#define HC   128        // H*C_OUT
#define NEG  0.2f
#define PR   8          // rows per proj group
#define NPROJ (Nn / PR)             // 1250 proj groups
#define LOG2E 1.44269504088896f

#define GRID  296       // 2 blocks per SM (148 SMs), co-resident by launch_bounds
#define TPB   640
#define NWRP  20        // warps per block
#define GRPS  5         // 128-thread proj groups per block
#define CHUNK 34        // nodes per block in scan (296*34 >= 10000)

// ---- device scratch (allocation-free rule: __device__ globals) ----
__device__ __align__(16) __half g_emb_h[Nn * HC];     // fp16 projected embedding [N,128]
__device__ __align__(16) float g_asrc[Nn * 4];        // src logits * log2e [N,H]
__device__ __align__(16) float g_adst[Nn * 4];        // dst logits * log2e [N,H]
__device__ __align__(16) int g_xT[Nn * Gg];           // transposed x: [N,16]
__device__ __align__(16) float2 g_comb[Nn * Gg * 4];  // per (n,g,h): {u_bits, asrc[u][h]}
__device__ int g_row_ptr[Nn + 1];
__device__ int g_cursor[Nn];                          // INVARIANT: all-zero at launch entry
__device__ int g_edge_src[Ee + 4];                    // +4 pad (stays 0) for 4-deep prefetch
__device__ int g_bsum[GRID];

// grid barrier: count self-resets; gen is monotonic across launches (replay-safe)
__device__ unsigned g_bcount = 0;
__device__ volatile unsigned g_bgen = 0;

__device__ __forceinline__ void grid_bar() {
    __syncthreads();
    if (threadIdx.x == 0) {
        __threadfence();
        unsigned my = g_bgen;
        unsigned t = atomicAdd(&g_bcount, 1);
        if (t == GRID - 1) {
            g_bcount = 0;
            __threadfence();
            g_bgen = my + 1;
        } else {
            while (g_bgen == my) { }
            __threadfence();
        }
    }
    __syncthreads();
}

__device__ __forceinline__ float fexp2(float x) {
    float y;
    asm("ex2.approx.f32 %0, %1;" : "=f"(y) : "f"(x));
    return y;
}

__global__ void __launch_bounds__(TPB, 2)
k_all(const float* __restrict__ emb, const float* __restrict__ W,
      const float* __restrict__ att_s, const float* __restrict__ att_d,
      const int* __restrict__ x, const int* __restrict__ adj,
      const float* __restrict__ bias, float* __restrict__ out) {
    int tid = threadIdx.x;
    int b = blockIdx.x;

    __shared__ float sws[256];            // fused W@att: [k][(srcdst<<2)|h]
    __shared__ float se[GRPS][PR][32];
    __shared__ int svals[CHUNK];
    __shared__ int soff;

    // ================= Phase A: histogram + projection + x-transpose =================
    for (int e = b * TPB + tid; e < Ee; e += GRID * TPB)
        atomicAdd(&g_cursor[adj[Ee + e]], 1);          // adj[1] = dst

    if (tid < 256) {
        int k = tid >> 3, j = tid & 7, h = j & 3;
        const float* av = (j < 4) ? att_s : att_d;
        float a = 0.f;
#pragma unroll
        for (int c2 = 0; c2 < 32; c2++)
            a = fmaf(W[k * 128 + h * 32 + c2], av[h * 32 + c2], a);
        sws[tid] = a;
    }
    __syncthreads();

    {
        int grp = tid >> 7;          // 0..4
        int c = tid & 127;           // channel 0..127
        int gb = b * GRPS + grp;     // 296*5 = 1480 >= 1250 -> single pass
        bool act = gb < NPROJ;
        int n0 = gb * PR;
        if (act) {
#pragma unroll
            for (int i = 0; i < 2; i++) {
                int idx = i * 128 + c;
                se[grp][idx >> 5][idx & 31] = emb[n0 * 32 + idx];
            }
            int gg = c >> 3, i = c & 7;
            g_xT[(n0 + i) * Gg + gg] = x[gg * Nn + n0 + i];
        }
        asm volatile("bar.sync %0, %1;" :: "r"(grp + 1), "r"(128));
        if (act) {
            float acc[PR];
#pragma unroll
            for (int r = 0; r < PR; r++) acc[r] = 0.f;
#pragma unroll
            for (int pass = 0; pass < 2; pass++) {
                float wcol[16];
#pragma unroll
                for (int k = 0; k < 16; k++) wcol[k] = W[(pass * 16 + k) * 128 + c];
#pragma unroll
                for (int r = 0; r < PR; r++) {
#pragma unroll
                    for (int k = 0; k < 16; k++)
                        acc[r] = fmaf(se[grp][r][pass * 16 + k], wcol[k], acc[r]);
                }
            }
#pragma unroll
            for (int r = 0; r < PR; r++)
                g_emb_h[(n0 + r) * 128 + c] = __float2half(acc[r]);
            if (c < 64) {
                int r = c >> 3, j = c & 7, h = j & 3;
                float a = 0.f;
#pragma unroll
                for (int k = 0; k < 32; k++) a = fmaf(se[grp][r][k], sws[k * 8 + j], a);
                a *= LOG2E;
                if (j < 4) g_asrc[(n0 + r) * 4 + h] = a;
                else       g_adst[(n0 + r) * 4 + h] = a;
            }
        }
    }
    grid_bar();   // ---- barrier 1: histogram + asrc + xT complete ----

    // ================= Phase B: CSR scan (warp 0) + comb table (all threads) =================
    if (tid < 32) {
        int lane = tid;
        int i0 = b * CHUNK + lane * 2;
        int c0 = (lane < 17 && i0 < Nn) ? g_cursor[i0] : 0;
        int c1 = (lane < 17 && i0 + 1 < Nn) ? g_cursor[i0 + 1] : 0;
        int lsum = c0 + c1;
        int pre = lsum;
#pragma unroll
        for (int o = 1; o < 32; o <<= 1) {
            int t = __shfl_up_sync(0xffffffffu, pre, o);
            if (lane >= o) pre += t;
        }
        int excl = pre - lsum;
        if (lane < 17) {
            svals[lane * 2] = excl;
            if (lane * 2 + 1 < CHUNK) svals[lane * 2 + 1] = excl + c0;
        }
        if (lane == 31) g_bsum[b] = pre;   // block total
    }

    // comb: per (n,g): u = xT[n*16+g]; entries h=0..3: {u_bits, asrc[u][h]}
    for (int i = b * TPB + tid; i < Nn * Gg; i += GRID * TPB) {
        int u = g_xT[i];
        float4 a4 = *(const float4*)(g_asrc + u * 4);
        float uf = __int_as_float(u);
        float4* dst = (float4*)(g_comb + i * 4);
        dst[0] = make_float4(uf, a4.x, uf, a4.y);
        dst[1] = make_float4(uf, a4.z, uf, a4.w);
    }
    grid_bar();   // ---- barrier 2: block sums + comb visible ----

    if (tid < 32) {
        int lane = tid;
        int acc = 0;
        for (int i = lane; i < b; i += 32) acc += g_bsum[i];
#pragma unroll
        for (int o = 16; o; o >>= 1) acc += __shfl_down_sync(0xffffffffu, acc, o);
        if (lane == 0) soff = acc;
    }
    __syncthreads();
    {
        int off = soff;
        if (tid < CHUNK) {
            int n = b * CHUNK + tid;
            if (n < Nn) {
                int p = off + svals[tid];
                g_row_ptr[n] = p;
                g_cursor[n] = p;
            }
        }
        if (b == 0 && tid == 0) g_row_ptr[Nn] = Ee;
    }
    grid_bar();   // ---- barrier 3: row_ptr/cursor ready ----

    // ================= Phase C: CSR fill =================
    for (int e = b * TPB + tid; e < Ee; e += GRID * TPB) {
        int d = adj[Ee + e];
        int p = atomicAdd(&g_cursor[d], 1);
        g_edge_src[p] = adj[e];          // adj[0] = src
    }
    grid_bar();   // ---- barrier 4: edge_src ready ----

    // ================= Phase D: GAT (persistent warps, 2 graphs per warp) =================
    for (int n = b * TPB + tid; n < Nn; n += GRID * TPB) g_cursor[n] = 0;  // restore invariant

    int lane = tid & 31;
    int gi = lane >> 4;          // graph within 2-chunk
    int sub = lane & 15;         // channel group: [8*sub, 8*sub+8)
    int h = sub >> 2;            // head
    bool pfl = (sub & 7) == 0;   // 4 prefetch lanes/warp: one per needed 128B line
    const __half* __restrict__ embp = g_emb_h;
    const float2* __restrict__ comb = g_comb;

    for (int w = b * NWRP + (tid >> 5); w < Nn * 8; w += GRID * NWRP) {
        int v = w >> 3;              // consecutive warps share v -> L1 hits
        int gc = w & 7;              // 2-graph chunk
        int g = gc * 2 + gi;
        int co = g * 4 + h;          // lane's comb entry within node's 64-entry row

        // self loop via comb
        float2 uav = comb[v * 64 + co];
        int vemb = __float_as_int(uav.x);
        float adst = g_adst[vemb * 4 + h];

        float acc[8];
        float s;
        {
            float a0 = uav.y + adst;
            a0 = fmaxf(a0, NEG * a0);
            float e0 = fexp2(a0);
            s = e0;
            uint4 q = *(const uint4*)(embp + vemb * 128 + sub * 8);
            const __half2* hp = (const __half2*)&q;
#pragma unroll
            for (int k = 0; k < 4; k++) {
                float2 f = __half22float2(hp[k]);
                acc[2 * k] = e0 * f.x;
                acc[2 * k + 1] = e0 * f.y;
            }
        }

        int idx = g_row_ptr[v];
        int end = g_row_ptr[v + 1];
        // deep pipeline: edge_src +4, comb +3, msg +2 (pad slots read 0 -> valid node 0)
        int j0 = g_edge_src[idx];
        int j1 = g_edge_src[idx + 1];
        int j2 = g_edge_src[idx + 2];
        float2 c0 = comb[j0 * 64 + co];
        float2 c1 = comb[j1 * 64 + co];
        float2 c2 = comb[j2 * 64 + co];
        uint4 m0 = *(const uint4*)(embp + __float_as_int(c0.x) * 128 + sub * 8);
        uint4 m1 = *(const uint4*)(embp + __float_as_int(c1.x) * 128 + sub * 8);
        int j3 = g_edge_src[idx + 3];
        for (; idx < end; idx++) {
            // register-free L1 prefetch of edge i+2's msg lines (addr from c2)
            if (pfl)
                asm volatile("prefetch.global.L1 [%0];"
                             :: "l"(embp + __float_as_int(c2.x) * 128 + sub * 8));
            // prefetch: msg for edge i+2 real-load next iter hits L1; comb for i+3; edge_src i+4
            uint4 m2 = *(const uint4*)(embp + __float_as_int(c2.x) * 128 + sub * 8);
            float2 cn = comb[j3 * 64 + co];
            j3 = g_edge_src[idx + 4];

            float a = c0.y + adst;
            a = fmaxf(a, NEG * a);
            float wi = fexp2(a);
            s += wi;
            const __half2* hp = (const __half2*)&m0;
#pragma unroll
            for (int k = 0; k < 4; k++) {
                float2 f = __half22float2(hp[k]);
                acc[2 * k]     = fmaf(wi, f.x, acc[2 * k]);
                acc[2 * k + 1] = fmaf(wi, f.y, acc[2 * k + 1]);
            }
            c0 = c1; c1 = c2; c2 = cn;
            m0 = m1; m1 = m2;
        }

        float inv = __fdividef(1.f, s + 1e-16f);
        float* op = out + ((size_t)g * Nn + v) * 128 + sub * 8;
        const float* bp = bias + sub * 8;
#pragma unroll
        for (int k = 0; k < 2; k++) {
            float4 bb = *(const float4*)(bp + 4 * k);
            float4 o;
            o.x = fmaf(acc[4 * k], inv, bb.x);
            o.y = fmaf(acc[4 * k + 1], inv, bb.y);
            o.z = fmaf(acc[4 * k + 2], inv, bb.z);
            o.w = fmaf(acc[4 * k + 3], inv, bb.w);
            *(float4*)(op + 4 * k) = o;
        }
    }
}

extern "C" void kernel_launch(void* const* d_in, const int* in_sizes, int n_in,
                              void* d_out, int out_size) {
    const int*   x     = (const int*)d_in[0];     // [B,DAYS,N] = [16,10000]
    const int*   adj   = (const int*)d_in[1];     // [2,E]
    const float* emb   = (const float*)d_in[2];   // [N,32]
    const float* W     = (const float*)d_in[3];   // [32,128]
    const float* att_s = (const float*)d_in[4];   // [4,32]
    const float* att_d = (const float*)d_in[5];   // [4,32]
    const float* bias  = (const float*)d_in[6];   // [128]
    float* out = (float*)d_out;                   // [16,10000,128]

    k_all<<<GRID, TPB>>>(emb, W, att_s, att_d, x, adj, bias, out);
}

// round 15
// speedup vs baseline: 1.0496x; 1.0496x over previous
#include <cuda_runtime.h>
#include <cuda_fp16.h>

// Problem constants (fixed by the reference)
#define Nn   10000      // nodes
#define Ee   80000      // edges (excl. self loops)
#define Gg   16         // B*DAYS graphs
#define HC   128        // H*C_OUT
#define NEG  0.2f
#define PR   8          // rows per proj group
#define NPROJ (Nn / PR)             // 1250 proj groups
#define LOG2E 1.44269504088896f

#define GRID  296       // 2 blocks per SM (148 SMs), co-resident by launch_bounds
#define TPB   640
#define NWRP  20        // warps per block
#define GRPS  5         // 128-thread proj groups per block
#define CHUNK 34        // nodes per block in scan (296*34 >= 10000)

// ---- device scratch (allocation-free rule: __device__ globals) ----
__device__ __align__(16) __half g_emb_h[Nn * HC];     // fp16 projected embedding [N,128]
__device__ __align__(16) float g_asrc[Nn * 4];        // src logits * log2e [N,H]
__device__ __align__(16) float g_adst[Nn * 4];        // dst logits * log2e [N,H]
__device__ __align__(16) int g_xT[Nn * Gg];           // transposed x: [N,16]
__device__ __align__(16) float2 g_comb[Nn * Gg * 4];  // per (n,g,h): {u*256 (byte off), asrc[u][h]}
__device__ int g_row_ptr[Nn + 1];
__device__ int g_cursor[Nn];                          // INVARIANT: all-zero at launch entry
__device__ int g_edge_src[Ee + 4];                    // +4 pad (stays 0) for deep prefetch
__device__ int g_bsum[GRID];

// grid barrier: count self-resets; gen is monotonic across launches (replay-safe)
__device__ unsigned g_bcount = 0;
__device__ volatile unsigned g_bgen = 0;

__device__ __forceinline__ void grid_bar() {
    __syncthreads();
    if (threadIdx.x == 0) {
        __threadfence();
        unsigned my = g_bgen;
        unsigned t = atomicAdd(&g_bcount, 1);
        if (t == GRID - 1) {
            g_bcount = 0;
            __threadfence();
            g_bgen = my + 1;
        } else {
            while (g_bgen == my) { }
            __threadfence();
        }
    }
    __syncthreads();
}

__device__ __forceinline__ float fexp2(float x) {
    float y;
    asm("ex2.approx.f32 %0, %1;" : "=f"(y) : "f"(x));
    return y;
}

__global__ void __launch_bounds__(TPB, 2)
k_all(const float* __restrict__ emb, const float* __restrict__ W,
      const float* __restrict__ att_s, const float* __restrict__ att_d,
      const int* __restrict__ x, const int* __restrict__ adj,
      const float* __restrict__ bias, float* __restrict__ out) {
    int tid = threadIdx.x;
    int b = blockIdx.x;

    __shared__ float sws[256];            // fused W@att: [k][(srcdst<<2)|h]
    __shared__ float se[GRPS][PR][32];
    __shared__ int svals[CHUNK];
    __shared__ int soff;

    // ================= Phase A: histogram + projection + x-transpose =================
    for (int e = b * TPB + tid; e < Ee; e += GRID * TPB)
        atomicAdd(&g_cursor[adj[Ee + e]], 1);          // adj[1] = dst

    if (tid < 256) {
        int k = tid >> 3, j = tid & 7, h = j & 3;
        const float* av = (j < 4) ? att_s : att_d;
        float a = 0.f;
#pragma unroll
        for (int c2 = 0; c2 < 32; c2++)
            a = fmaf(W[k * 128 + h * 32 + c2], av[h * 32 + c2], a);
        sws[tid] = a;
    }
    __syncthreads();

    {
        int grp = tid >> 7;          // 0..4
        int c = tid & 127;           // channel 0..127
        int gb = b * GRPS + grp;     // 296*5 = 1480 >= 1250 -> single pass
        bool act = gb < NPROJ;
        int n0 = gb * PR;
        if (act) {
#pragma unroll
            for (int i = 0; i < 2; i++) {
                int idx = i * 128 + c;
                se[grp][idx >> 5][idx & 31] = emb[n0 * 32 + idx];
            }
            int gg = c >> 3, i = c & 7;
            g_xT[(n0 + i) * Gg + gg] = x[gg * Nn + n0 + i];
        }
        asm volatile("bar.sync %0, %1;" :: "r"(grp + 1), "r"(128));
        if (act) {
            float acc[PR];
#pragma unroll
            for (int r = 0; r < PR; r++) acc[r] = 0.f;
#pragma unroll
            for (int pass = 0; pass < 2; pass++) {
                float wcol[16];
#pragma unroll
                for (int k = 0; k < 16; k++) wcol[k] = W[(pass * 16 + k) * 128 + c];
#pragma unroll
                for (int r = 0; r < PR; r++) {
#pragma unroll
                    for (int k = 0; k < 16; k++)
                        acc[r] = fmaf(se[grp][r][pass * 16 + k], wcol[k], acc[r]);
                }
            }
#pragma unroll
            for (int r = 0; r < PR; r++)
                g_emb_h[(n0 + r) * 128 + c] = __float2half(acc[r]);
            if (c < 64) {
                int r = c >> 3, j = c & 7, h = j & 3;
                float a = 0.f;
#pragma unroll
                for (int k = 0; k < 32; k++) a = fmaf(se[grp][r][k], sws[k * 8 + j], a);
                a *= LOG2E;
                if (j < 4) g_asrc[(n0 + r) * 4 + h] = a;
                else       g_adst[(n0 + r) * 4 + h] = a;
            }
        }
    }
    grid_bar();   // ---- barrier 1: histogram + asrc + xT complete ----

    // ================= Phase B: CSR scan (warp 0) + comb table (all threads) =================
    if (tid < 32) {
        int lane = tid;
        int i0 = b * CHUNK + lane * 2;
        int c0 = (lane < 17 && i0 < Nn) ? g_cursor[i0] : 0;
        int c1 = (lane < 17 && i0 + 1 < Nn) ? g_cursor[i0 + 1] : 0;
        int lsum = c0 + c1;
        int pre = lsum;
#pragma unroll
        for (int o = 1; o < 32; o <<= 1) {
            int t = __shfl_up_sync(0xffffffffu, pre, o);
            if (lane >= o) pre += t;
        }
        int excl = pre - lsum;
        if (lane < 17) {
            svals[lane * 2] = excl;
            if (lane * 2 + 1 < CHUNK) svals[lane * 2 + 1] = excl + c0;
        }
        if (lane == 31) g_bsum[b] = pre;   // block total
    }

    // comb: per (n,g): u = xT[n*16+g]; entries h=0..3: {byte offset u*256, asrc[u][h]}
    for (int i = b * TPB + tid; i < Nn * Gg; i += GRID * TPB) {
        int u = g_xT[i];
        float4 a4 = *(const float4*)(g_asrc + u * 4);
        float uf = __int_as_float(u << 8);   // u * 256 bytes (fp16 row stride)
        float4* dst = (float4*)(g_comb + i * 4);
        dst[0] = make_float4(uf, a4.x, uf, a4.y);
        dst[1] = make_float4(uf, a4.z, uf, a4.w);
    }
    grid_bar();   // ---- barrier 2: block sums + comb visible ----

    if (tid < 32) {
        int lane = tid;
        int acc = 0;
        for (int i = lane; i < b; i += 32) acc += g_bsum[i];
#pragma unroll
        for (int o = 16; o; o >>= 1) acc += __shfl_down_sync(0xffffffffu, acc, o);
        if (lane == 0) soff = acc;
    }
    __syncthreads();
    {
        int off = soff;
        if (tid < CHUNK) {
            int n = b * CHUNK + tid;
            if (n < Nn) {
                int p = off + svals[tid];
                g_row_ptr[n] = p;
                g_cursor[n] = p;
            }
        }
        if (b == 0 && tid == 0) g_row_ptr[Nn] = Ee;
    }
    grid_bar();   // ---- barrier 3: row_ptr/cursor ready ----

    // ================= Phase C: CSR fill =================
    for (int e = b * TPB + tid; e < Ee; e += GRID * TPB) {
        int d = adj[Ee + e];
        int p = atomicAdd(&g_cursor[d], 1);
        g_edge_src[p] = adj[e];          // adj[0] = src
    }
    grid_bar();   // ---- barrier 4: edge_src ready ----

    // ================= Phase D: GAT (persistent warps, 2 graphs per warp) =================
    for (int n = b * TPB + tid; n < Nn; n += GRID * TPB) g_cursor[n] = 0;  // restore invariant

    int lane = tid & 31;
    int gi = lane >> 4;          // graph within 2-chunk
    int sub = lane & 15;         // channel group: [8*sub, 8*sub+8)
    int h = sub >> 2;            // head
    const char* __restrict__ embb = (const char*)g_emb_h;
    const float2* __restrict__ comb = g_comb;
    int lby = sub * 16;          // lane byte offset within a 256B msg row

#define PROC(cc, mm) do { \
        float a_ = (cc).y + adst; \
        a_ = fmaxf(a_, NEG * a_); \
        float wi_ = fexp2(a_); \
        s += wi_; \
        const __half2* hp_ = (const __half2*)&(mm); \
        _Pragma("unroll") \
        for (int k_ = 0; k_ < 4; k_++) { \
            float2 f_ = __half22float2(hp_[k_]); \
            acc[2 * k_]     = fmaf(wi_, f_.x, acc[2 * k_]); \
            acc[2 * k_ + 1] = fmaf(wi_, f_.y, acc[2 * k_ + 1]); \
        } \
    } while (0)

    for (int w = b * NWRP + (tid >> 5); w < Nn * 8; w += GRID * NWRP) {
        int v = w >> 3;              // consecutive warps share v -> L1 hits
        int gc = w & 7;              // 2-graph chunk
        int g = gc * 2 + gi;
        int co = g * 4 + h;          // lane's comb entry within node's 64-entry row

        // self loop via comb
        float2 uav = comb[v * 64 + co];
        int voff = __float_as_int(uav.x);    // u*256
        float adst = *(const float*)((const char*)g_adst + (voff >> 4) + h * 4);

        float acc[8];
        float s;
        {
            float a0 = uav.y + adst;
            a0 = fmaxf(a0, NEG * a0);
            float e0 = fexp2(a0);
            s = e0;
            uint4 q = *(const uint4*)(embb + voff + lby);
            const __half2* hp = (const __half2*)&q;
#pragma unroll
            for (int k = 0; k < 4; k++) {
                float2 f = __half22float2(hp[k]);
                acc[2 * k] = e0 * f.x;
                acc[2 * k + 1] = e0 * f.y;
            }
        }

        int idx = g_row_ptr[v];
        int end = g_row_ptr[v + 1];
        // 2x-unrolled software pipeline; pad slots read 0 -> node 0 (valid, unused)
        int ja = g_edge_src[idx];
        int jb = g_edge_src[idx + 1];
        int jc = g_edge_src[idx + 2];
        float2 c0 = comb[ja * 64 + co];
        float2 c1 = comb[jb * 64 + co];
        float2 c2 = comb[jc * 64 + co];
        uint4 m0 = *(const uint4*)(embb + __float_as_int(c0.x) + lby);
        uint4 m1 = *(const uint4*)(embb + __float_as_int(c1.x) + lby);
        int jd = g_edge_src[idx + 3];
        int cnt = end - idx;
        while (cnt >= 2) {
            // stage 1: edge i
            uint4 m2 = *(const uint4*)(embb + __float_as_int(c2.x) + lby);
            float2 c3 = comb[jd * 64 + co];
            int je = g_edge_src[idx + 4];
            PROC(c0, m0);
            // stage 2: edge i+1
            uint4 m3 = *(const uint4*)(embb + __float_as_int(c3.x) + lby);
            float2 c4 = comb[je * 64 + co];
            jd = g_edge_src[idx + 5];
            PROC(c1, m1);
            // rotate (even period -> ptxas renames most of this away)
            c0 = c2; c1 = c3; c2 = c4;
            m0 = m2; m1 = m3;
            idx += 2;
            cnt -= 2;
        }
        if (cnt) PROC(c0, m0);

        float inv = __fdividef(1.f, s + 1e-16f);
        float* op = out + ((size_t)g * Nn + v) * 128 + sub * 8;
        const float* bp = bias + sub * 8;
#pragma unroll
        for (int k = 0; k < 2; k++) {
            float4 bb = *(const float4*)(bp + 4 * k);
            float4 o;
            o.x = fmaf(acc[4 * k], inv, bb.x);
            o.y = fmaf(acc[4 * k + 1], inv, bb.y);
            o.z = fmaf(acc[4 * k + 2], inv, bb.z);
            o.w = fmaf(acc[4 * k + 3], inv, bb.w);
            *(float4*)(op + 4 * k) = o;
        }
    }
#undef PROC
}

extern "C" void kernel_launch(void* const* d_in, const int* in_sizes, int n_in,
                              void* d_out, int out_size) {
    const int*   x     = (const int*)d_in[0];     // [B,DAYS,N] = [16,10000]
    const int*   adj   = (const int*)d_in[1];     // [2,E]
    const float* emb   = (const float*)d_in[2];   // [N,32]
    const float* W     = (const float*)d_in[3];   // [32,128]
    const float* att_s = (const float*)d_in[4];   // [4,32]
    const float* att_d = (const float*)d_in[5];   // [4,32]
    const float* bias  = (const float*)d_in[6];   // [128]
    float* out = (float*)d_out;                   // [16,10000,128]

    k_all<<<GRID, TPB>>>(emb, W, att_s, att_d, x, adj, bias, out);
}

// round 16
// speedup vs baseline: 1.2392x; 1.1806x over previous
#include <cuda_runtime.h>
#include <cuda_fp16.h>

// Problem constants (fixed by the reference)
#define Nn   10000      // nodes
#define Ee   80000      // edges (excl. self loops)
#define Gg   16         // B*DAYS graphs
#define HC   128        // H*C_OUT
#define NEG  0.2f
#define PR   8          // rows per proj group
#define NPROJ (Nn / PR)             // 1250 proj groups
#define LOG2E 1.44269504088896f
#define ESTR 64         // ELL stride (max degree headroom; Poisson(8) max ~25)

#define GRID  296       // 2 blocks per SM (148 SMs), co-resident by launch_bounds
#define TPB   640
#define NWRP  20        // warps per block
#define GRPS  5         // 128-thread proj groups per block

// ---- device scratch (allocation-free rule: __device__ globals) ----
__device__ __align__(16) __half g_emb_h[Nn * HC];     // fp16 projected embedding [N,128]
__device__ __align__(16) float g_asrc[Nn * 4];        // src logits * log2e [N,H]
__device__ __align__(16) float g_adst[Nn * 4];        // dst logits * log2e [N,H]
__device__ __align__(16) int g_xT[Nn * Gg];           // transposed x: [N,16]
__device__ __align__(16) float2 g_comb[Nn * Gg * 4];  // per (n,g,h): {u_bits, asrc[u][h]}
__device__ __align__(16) float g_adst_t[Nn * Gg * 4]; // per (n,g,h): adst[x[g][n]][h]
__device__ int g_ell[Nn * ESTR + 8];                  // ELL edge lists (tail slots stay 0)
__device__ int g_deg[Nn];
__device__ int g_cursor[Nn];                          // INVARIANT: all-zero at launch entry

// grid barrier: count self-resets; gen is monotonic across launches (replay-safe)
__device__ unsigned g_bcount = 0;
__device__ volatile unsigned g_bgen = 0;

__device__ __forceinline__ void grid_bar() {
    __syncthreads();
    if (threadIdx.x == 0) {
        __threadfence();
        unsigned my = g_bgen;
        unsigned t = atomicAdd(&g_bcount, 1);
        if (t == GRID - 1) {
            g_bcount = 0;
            __threadfence();
            g_bgen = my + 1;
        } else {
            while (g_bgen == my) { }
            __threadfence();
        }
    }
    __syncthreads();
}

__device__ __forceinline__ float fexp2(float x) {
    float y;
    asm("ex2.approx.f32 %0, %1;" : "=f"(y) : "f"(x));
    return y;
}

__global__ void __launch_bounds__(TPB, 2)
k_all(const float* __restrict__ emb, const float* __restrict__ W,
      const float* __restrict__ att_s, const float* __restrict__ att_d,
      const int* __restrict__ x, const int* __restrict__ adj,
      const float* __restrict__ bias, float* __restrict__ out) {
    int tid = threadIdx.x;
    int b = blockIdx.x;

    __shared__ float sws[256];            // fused W@att: [k][(srcdst<<2)|h]
    __shared__ float se[GRPS][PR][32];

    // ================= Phase A: ELL edge fill + projection + x-transpose =================
    // ELL fill: independent of projection; atomics overlap proj compute
    for (int e = b * TPB + tid; e < Ee; e += GRID * TPB) {
        int d = adj[Ee + e];               // adj[1] = dst
        int p = atomicAdd(&g_cursor[d], 1);
        if (p < ESTR) g_ell[d * ESTR + p] = adj[e];   // adj[0] = src
    }

    if (tid < 256) {
        int k = tid >> 3, j = tid & 7, h = j & 3;
        const float* av = (j < 4) ? att_s : att_d;
        float a = 0.f;
#pragma unroll
        for (int c2 = 0; c2 < 32; c2++)
            a = fmaf(W[k * 128 + h * 32 + c2], av[h * 32 + c2], a);
        sws[tid] = a;
    }
    __syncthreads();

    {
        int grp = tid >> 7;          // 0..4
        int c = tid & 127;           // channel 0..127
        int gb = b * GRPS + grp;     // 296*5 = 1480 >= 1250 -> single pass
        bool act = gb < NPROJ;
        int n0 = gb * PR;
        if (act) {
#pragma unroll
            for (int i = 0; i < 2; i++) {
                int idx = i * 128 + c;
                se[grp][idx >> 5][idx & 31] = emb[n0 * 32 + idx];
            }
            int gg = c >> 3, i = c & 7;
            g_xT[(n0 + i) * Gg + gg] = x[gg * Nn + n0 + i];
        }
        asm volatile("bar.sync %0, %1;" :: "r"(grp + 1), "r"(128));
        if (act) {
            float acc[PR];
#pragma unroll
            for (int r = 0; r < PR; r++) acc[r] = 0.f;
#pragma unroll
            for (int pass = 0; pass < 2; pass++) {
                float wcol[16];
#pragma unroll
                for (int k = 0; k < 16; k++) wcol[k] = W[(pass * 16 + k) * 128 + c];
#pragma unroll
                for (int r = 0; r < PR; r++) {
#pragma unroll
                    for (int k = 0; k < 16; k++)
                        acc[r] = fmaf(se[grp][r][pass * 16 + k], wcol[k], acc[r]);
                }
            }
#pragma unroll
            for (int r = 0; r < PR; r++)
                g_emb_h[(n0 + r) * 128 + c] = __float2half(acc[r]);
            if (c < 64) {
                int r = c >> 3, j = c & 7, h = j & 3;
                float a = 0.f;
#pragma unroll
                for (int k = 0; k < 32; k++) a = fmaf(se[grp][r][k], sws[k * 8 + j], a);
                a *= LOG2E;
                if (j < 4) g_asrc[(n0 + r) * 4 + h] = a;
                else       g_adst[(n0 + r) * 4 + h] = a;
            }
        }
    }
    grid_bar();   // ---- barrier 1: ELL fill + asrc/adst + xT complete ----

    // ================= Phase B: deg copy + cursor reset + comb/adst_t build =================
    for (int n = b * TPB + tid; n < Nn; n += GRID * TPB) {
        g_deg[n] = g_cursor[n];
        g_cursor[n] = 0;                 // restore invariant for next launch/replay
    }
    // comb: per (n,g): u = xT[n*16+g]; entries h=0..3: {u_bits, asrc[u][h]}; adst_t: adst[u][h]
    for (int i = b * TPB + tid; i < Nn * Gg; i += GRID * TPB) {
        int u = g_xT[i];
        float4 a4 = *(const float4*)(g_asrc + u * 4);
        float4 d4 = *(const float4*)(g_adst + u * 4);
        float uf = __int_as_float(u);
        float4* dst = (float4*)(g_comb + i * 4);
        dst[0] = make_float4(uf, a4.x, uf, a4.y);
        dst[1] = make_float4(uf, a4.z, uf, a4.w);
        *(float4*)(g_adst_t + i * 4) = d4;
    }
    grid_bar();   // ---- barrier 2: deg + comb + adst_t visible ----

    // ================= Phase D: GAT (persistent warps, 2 graphs per warp) =================
    int lane = tid & 31;
    int gi = lane >> 4;          // graph within 2-chunk
    int sub = lane & 15;         // channel group: [8*sub, 8*sub+8)
    int h = sub >> 2;            // head
    const __half* __restrict__ embp = g_emb_h;
    const float2* __restrict__ comb = g_comb;

    for (int w = b * NWRP + (tid >> 5); w < Nn * 8; w += GRID * NWRP) {
        int v = w >> 3;              // consecutive warps share v -> L1 hits
        int gc = w & 7;              // 2-graph chunk
        int g = gc * 2 + gi;
        int co = g * 4 + h;          // lane's comb entry within node's 64-entry row
        int base = v * ESTR;

        // edge index prefetches first: no dependency, maximal overlap with prologue
        int j0 = g_ell[base];
        int j1 = g_ell[base + 1];
        int j2 = g_ell[base + 2];
        int deg = g_deg[v];
        float2 uav = comb[v * 64 + co];
        float adst = g_adst_t[v * 64 + co];

        float2 c0 = comb[j0 * 64 + co];
        float2 c1 = comb[j1 * 64 + co];
        float2 c2 = comb[j2 * 64 + co];
        int vemb = __float_as_int(uav.x);

        float acc[8];
        float s;
        {
            float a0 = uav.y + adst;
            a0 = fmaxf(a0, NEG * a0);
            float e0 = fexp2(a0);
            s = e0;
            uint4 q = *(const uint4*)(embp + vemb * 128 + sub * 8);
            const __half2* hp = (const __half2*)&q;
#pragma unroll
            for (int k = 0; k < 4; k++) {
                float2 f = __half22float2(hp[k]);
                acc[2 * k] = e0 * f.x;
                acc[2 * k + 1] = e0 * f.y;
            }
        }

        // deep pipeline: ell +4, comb +3, msg +2 (unwritten ELL slots stay 0 -> valid node 0)
        uint4 m0 = *(const uint4*)(embp + __float_as_int(c0.x) * 128 + sub * 8);
        uint4 m1 = *(const uint4*)(embp + __float_as_int(c1.x) * 128 + sub * 8);
        int j3 = g_ell[base + 3];
        for (int idx = 0; idx < deg; idx++) {
            uint4 m2 = *(const uint4*)(embp + __float_as_int(c2.x) * 128 + sub * 8);
            float2 cn = comb[j3 * 64 + co];
            j3 = g_ell[base + idx + 4];

            float a = c0.y + adst;
            a = fmaxf(a, NEG * a);
            float wi = fexp2(a);
            s += wi;
            const __half2* hp = (const __half2*)&m0;
#pragma unroll
            for (int k = 0; k < 4; k++) {
                float2 f = __half22float2(hp[k]);
                acc[2 * k]     = fmaf(wi, f.x, acc[2 * k]);
                acc[2 * k + 1] = fmaf(wi, f.y, acc[2 * k + 1]);
            }
            c0 = c1; c1 = c2; c2 = cn;
            m0 = m1; m1 = m2;
        }

        float inv = __fdividef(1.f, s + 1e-16f);
        float* op = out + ((size_t)g * Nn + v) * 128 + sub * 8;
        const float* bp = bias + sub * 8;
#pragma unroll
        for (int k = 0; k < 2; k++) {
            float4 bb = *(const float4*)(bp + 4 * k);
            float4 o;
            o.x = fmaf(acc[4 * k], inv, bb.x);
            o.y = fmaf(acc[4 * k + 1], inv, bb.y);
            o.z = fmaf(acc[4 * k + 2], inv, bb.z);
            o.w = fmaf(acc[4 * k + 3], inv, bb.w);
            *(float4*)(op + 4 * k) = o;
        }
    }
}

extern "C" void kernel_launch(void* const* d_in, const int* in_sizes, int n_in,
                              void* d_out, int out_size) {
    const int*   x     = (const int*)d_in[0];     // [B,DAYS,N] = [16,10000]
    const int*   adj   = (const int*)d_in[1];     // [2,E]
    const float* emb   = (const float*)d_in[2];   // [N,32]
    const float* W     = (const float*)d_in[3];   // [32,128]
    const float* att_s = (const float*)d_in[4];   // [4,32]
    const float* att_d = (const float*)d_in[5];   // [4,32]
    const float* bias  = (const float*)d_in[6];   // [128]
    float* out = (float*)d_out;                   // [16,10000,128]

    k_all<<<GRID, TPB>>>(emb, W, att_s, att_d, x, adj, bias, out);
}